// round 15
// baseline (speedup 1.0000x reference)
#include <cuda_runtime.h>
#include <cuda_bf16.h>
#include <cuda_fp16.h>
#include <cstdint>

#define NN 100000
#define NE 600000
#define NR 3
#define NL 3
#define DIM 128
#define BN_EPS 1e-5f
#define MT ((NN + 127) / 128)   // 782 tiles

#if defined(__CUDA_ARCH_FEAT_SM103_ALL) || defined(__CUDA_ARCH_FEAT_SM100_ALL) || \
    defined(__CUDA_ARCH_FEAT_SM101_ALL) || \
    (defined(__CUDA_ARCH_FAMILY_SPECIFIC__) && (__CUDA_ARCH_FAMILY_SPECIFIC__ >= 1000)) || \
    (defined(__CUDA_ARCH_SPECIFIC__) && (__CUDA_ARCH_SPECIFIC__ >= 1000))
#define HAS_TCGEN05 1
#else
#define HAS_TCGEN05 0
#endif

// ---------------- scratch ----------------
__device__ __align__(16) float g_h[(size_t)NN * DIM];
__device__ __align__(16) __half g_m0[(size_t)NN * DIM];
__device__ __align__(16) __half g_m1[(size_t)NN * DIM];
__device__ __align__(16) __half g_m2[(size_t)NN * DIM];
__device__ __align__(16) float g_agg[(size_t)NN * DIM];
__device__ __align__(16) float g_dinv_o[NR * NN];
__device__ __align__(16) float g_dinv_i[NR * NN];
__device__ __align__(16) int g_cnt_in[NR * NN];
__device__ __align__(16) int g_cnt_out[NR * NN];
__device__ __align__(16) int g_cursor[NR * NN];
__device__ __align__(16) int g_excl[NR * NN];
__device__ __align__(16) int g_bsum[512];
__device__ __align__(16) int g_srcidx[NR * NE];
__device__ __align__(16) float g_stats3[NL * 2 * DIM];
__device__ __align__(16) uint8_t g_Wbf[12 * 65536];
__device__ __align__(16) float g_fceff[NL * DIM];

// ---------------- PTX helpers ----------------
__device__ __forceinline__ uint32_t smem_u32(const void* p) {
    uint32_t a;
    asm("{ .reg .u64 t; cvta.to.shared.u64 t, %1; cvt.u32.u64 %0, t; }" : "=r"(a) : "l"(p));
    return a;
}

#if HAS_TCGEN05
__device__ __forceinline__ uint32_t elect_one() {
    uint32_t pred;
    asm volatile("{\n\t.reg .pred p;\n\telect.sync _|p, 0xFFFFFFFF;\n\tselp.b32 %0, 1, 0, p;\n\t}" : "=r"(pred));
    return pred;
}
#define MBARRIER_INIT(addr, cnt) \
    asm volatile("mbarrier.init.shared.b64 [%0], %1;" :: "r"((uint32_t)(addr)), "r"((uint32_t)(cnt)) : "memory")
__device__ __forceinline__ void mbar_wait(uint32_t mbar, uint32_t parity) {
    asm volatile(
        "{\n\t.reg .pred P;\n\t"
        "WL_%=:\n\t"
        "mbarrier.try_wait.parity.acquire.cta.shared::cta.b64 P, [%0], %1, 0x989680;\n\t"
        "@P bra.uni WD_%=;\n\t"
        "bra.uni WL_%=;\n\t"
        "WD_%=:\n\t}"
        :: "r"(mbar), "r"(parity) : "memory");
}
#define TCGEN05_ALLOC(smem_addr, n) \
    asm volatile("tcgen05.alloc.cta_group::1.sync.aligned.shared::cta.b32 [%0], %1;" \
                 :: "r"((uint32_t)(smem_addr)), "r"((uint32_t)(n)) : "memory")
#define TCGEN05_DEALLOC(tmem, n) \
    asm volatile("tcgen05.dealloc.cta_group::1.sync.aligned.b32 %0, %1;" :: "r"(tmem), "r"((uint32_t)(n)))
#define TCGEN05_COMMIT(mbar) \
    asm volatile("tcgen05.commit.cta_group::1.mbarrier::arrive::one.shared::cluster.b64 [%0];" \
                 :: "r"((uint32_t)(mbar)) : "memory")
#define TCGEN05_WAIT_LD() asm volatile("tcgen05.wait::ld.sync.aligned;" ::: "memory")
#define TCGEN05_FENCE_AFTER() asm volatile("tcgen05.fence::after_thread_sync;" ::: "memory")
#define FENCE_ASYNC_SHARED() asm volatile("fence.proxy.async.shared::cta;" ::: "memory")

#define TCGEN05_LD_32X32B_X32(r, tmem_addr) \
    asm volatile( \
        "tcgen05.ld.sync.aligned.32x32b.x32.b32 " \
        "{%0, %1, %2, %3, %4, %5, %6, %7, " \
        " %8, %9, %10, %11, %12, %13, %14, %15, " \
        " %16, %17, %18, %19, %20, %21, %22, %23, " \
        " %24, %25, %26, %27, %28, %29, %30, %31}, [%32];" \
        : "=r"((r)[0]),  "=r"((r)[1]),  "=r"((r)[2]),  "=r"((r)[3]), \
          "=r"((r)[4]),  "=r"((r)[5]),  "=r"((r)[6]),  "=r"((r)[7]), \
          "=r"((r)[8]),  "=r"((r)[9]),  "=r"((r)[10]), "=r"((r)[11]), \
          "=r"((r)[12]), "=r"((r)[13]), "=r"((r)[14]), "=r"((r)[15]), \
          "=r"((r)[16]), "=r"((r)[17]), "=r"((r)[18]), "=r"((r)[19]), \
          "=r"((r)[20]), "=r"((r)[21]), "=r"((r)[22]), "=r"((r)[23]), \
          "=r"((r)[24]), "=r"((r)[25]), "=r"((r)[26]), "=r"((r)[27]), \
          "=r"((r)[28]), "=r"((r)[29]), "=r"((r)[30]), "=r"((r)[31]) \
        : "r"(tmem_addr))

static constexpr uint64_t SMEM_DESC_BASE_SW128 =
    (uint64_t(2) << 61) | (uint64_t(1) << 46) | (uint64_t(64) << 32) | (uint64_t(1) << 16);
#define MAKE_SMEM_DESC(base_addr) (SMEM_DESC_BASE_SW128 | ((uint64_t)((base_addr) >> 4) & 0x3FFF))

__device__ __forceinline__ void mma_f16_ss(uint32_t d, uint64_t a, uint64_t b, uint32_t idesc, int acc) {
    asm volatile(
        "{\n\t.reg .pred p;\n\tsetp.ne.u32 p, %4, 0;\n\t"
        "tcgen05.mma.cta_group::1.kind::f16 [%0], %1, %2, %3, {%5, %5, %5, %5}, p;\n\t}"
        :: "r"(d), "l"(a), "l"(b), "r"(idesc), "r"(acc), "r"(0u) : "memory");
}
#define MMA_IDESC 0x8200490u

// 3-pass hi/lo sweep: AhBh + AhBl + AlBh
__device__ __forceinline__ void mma_pass3(uint32_t d, uint64_t aH, uint64_t aL, uint64_t bH, uint64_t bL) {
    uint64_t ad[3] = {aH, aH, aL};
    uint64_t bd[3] = {bH, bL, bH};
#pragma unroll
    for (int p = 0; p < 3; p++)
#pragma unroll
        for (int s = 0; s < 8; s++) {
            uint64_t o = (s < 4) ? (uint64_t)(s * 2) : (uint64_t)(1024 + (s - 4) * 2);
            mma_f16_ss(d, ad[p] + o, bd[p] + o, MMA_IDESC, !(p == 0 && s == 0));
        }
}
#endif  // HAS_TCGEN05

// Blocked SW128 atom layout for a 128x128 bf16 tile.
__host__ __device__ __forceinline__ uint32_t tile_off(int row, int col) {
    uint32_t off = (uint32_t)(((row >> 3) + ((col >> 6) << 4)) << 10) | ((row & 7) << 7) | ((col & 63) << 1);
    return off ^ ((off >> 3) & 0x70);
}

__device__ __forceinline__ void split_store(char* base_hi, char* base_lo, uint32_t off, float4 v) {
    __nv_bfloat162 h01 = __floats2bfloat162_rn(v.x, v.y);
    __nv_bfloat162 h23 = __floats2bfloat162_rn(v.z, v.w);
    float lx = v.x - __bfloat162float(h01.x);
    float ly = v.y - __bfloat162float(h01.y);
    float lz = v.z - __bfloat162float(h23.x);
    float lw = v.w - __bfloat162float(h23.y);
    __nv_bfloat162 l01 = __floats2bfloat162_rn(lx, ly);
    __nv_bfloat162 l23 = __floats2bfloat162_rn(lz, lw);
    uint2 hv, lv;
    hv.x = *(uint32_t*)&h01; hv.y = *(uint32_t*)&h23;
    lv.x = *(uint32_t*)&l01; lv.y = *(uint32_t*)&l23;
    *(uint2*)(base_hi + off) = hv;
    *(uint2*)(base_lo + off) = lv;
}

__device__ __forceinline__ uint2 pack_half4(float4 v) {
    __half2 p0 = __floats2half2_rn(v.x, v.y);
    __half2 p1 = __floats2half2_rn(v.z, v.w);
    uint2 u;
    u.x = *(uint32_t*)&p0;
    u.y = *(uint32_t*)&p1;
    return u;
}

// ---------------- prep kernels ----------------
__global__ void __launch_bounds__(256) k_zeroprep(int* a, int* b, int* c, float* stats, int n) {
    int i = blockIdx.x * 256 + threadIdx.x;
    if (i < n) { a[i] = 0; b[i] = 0; c[i] = 0; }
    if (i < NL * 2 * DIM) stats[i] = 0.f;
}
__global__ void __launch_bounds__(256) k_cnt(const int* __restrict__ edges,
                                             int* __restrict__ cnt_out, int* __restrict__ cnt_in) {
    int i = blockIdx.x * 256 + threadIdx.x;
    if (i >= NR * NE) return;
    int r = i / NE;
    int e = i - r * NE;
    int s = edges[(size_t)(r * 2 + 0) * NE + e];
    int d = edges[(size_t)(r * 2 + 1) * NE + e];
    atomicAdd(&cnt_out[r * NN + s], 1);
    atomicAdd(&cnt_in[r * NN + d], 1);
}
__global__ void __launch_bounds__(256) k_dinv(const int* __restrict__ cnt_out, const int* __restrict__ cnt_in,
                                              float* __restrict__ dinv_o, float* __restrict__ dinv_i) {
    int i = blockIdx.x * 256 + threadIdx.x;
    if (i >= NR * NN) return;
    dinv_o[i] = rsqrtf(fmaxf((float)cnt_out[i], 1.f));
    dinv_i[i] = rsqrtf(fmaxf((float)cnt_in[i], 1.f));
}
__global__ void __launch_bounds__(1024) k_scan1(const int* __restrict__ cnt, int* __restrict__ excl,
                                                int* __restrict__ bsum, int N) {
    int i = blockIdx.x * 1024 + threadIdx.x;
    int lane = threadIdx.x & 31, warp = threadIdx.x >> 5;
    int x = (i < N) ? cnt[i] : 0;
    int v = x;
#pragma unroll
    for (int o = 1; o < 32; o <<= 1) { int y = __shfl_up_sync(~0u, v, o); if (lane >= o) v += y; }
    __shared__ int ws[32];
    if (lane == 31) ws[warp] = v;
    __syncthreads();
    if (warp == 0) {
        int w = ws[lane];
#pragma unroll
        for (int o = 1; o < 32; o <<= 1) { int y = __shfl_up_sync(~0u, w, o); if (lane >= o) w += y; }
        ws[lane] = w;
    }
    __syncthreads();
    int wexcl = (warp == 0) ? 0 : ws[warp - 1];
    if (i < N) excl[i] = wexcl + v - x;
    if (threadIdx.x == 1023) bsum[blockIdx.x] = ws[31];
}
__global__ void __launch_bounds__(512) k_scan2(int* __restrict__ bsum, int nb) {
    __shared__ int s[512];
    int tid = threadIdx.x;
    int v = (tid < nb) ? bsum[tid] : 0;
    s[tid] = v;
    __syncthreads();
    for (int o = 1; o < 512; o <<= 1) {
        int y = (tid >= o) ? s[tid - o] : 0;
        __syncthreads();
        s[tid] += y;
        __syncthreads();
    }
    if (tid < nb) bsum[tid] = s[tid] - v;
}
__global__ void __launch_bounds__(1024) k_scan3(int* __restrict__ excl, const int* __restrict__ bsum, int N) {
    int i = blockIdx.x * 1024 + threadIdx.x;
    if (i < N) excl[i] += bsum[blockIdx.x];
}
__global__ void __launch_bounds__(256) k_place(const int* __restrict__ edges, const int* __restrict__ excl,
                                               int* __restrict__ cursor, int* __restrict__ srcidx) {
    int i = blockIdx.x * 256 + threadIdx.x;
    if (i >= NR * NE) return;
    int r = i / NE;
    int e = i - r * NE;
    int s = edges[(size_t)(r * 2 + 0) * NE + e];
    int d = edges[(size_t)(r * 2 + 1) * NE + e];
    int pos = atomicAdd(&cursor[r * NN + d], 1);
    srcidx[excl[r * NN + d] + pos] = s;
}
__global__ void __launch_bounds__(256) k_wprep(const float* __restrict__ convW,
                                               const float* __restrict__ fcW,
                                               uint8_t* __restrict__ wbf) {
    int idx = blockIdx.x * 256 + threadIdx.x;
    if (idx >= 12 * 16384) return;
    int w = idx >> 14;
    int e = idx & 16383;
    int k = e >> 7, n = e & 127;
    const float* W = (w < 9) ? (convW + (size_t)w * 16384) : (fcW + (size_t)(w - 9) * 16384);
    float v = W[e];
    __nv_bfloat16 hi = __float2bfloat16(v);
    __nv_bfloat16 lo = __float2bfloat16(v - __bfloat162float(hi));
    uint32_t off = tile_off(n, k);
    *(__nv_bfloat16*)(wbf + (size_t)w * 65536 + off) = hi;
    *(__nv_bfloat16*)(wbf + (size_t)w * 65536 + 32768 + off) = lo;
}
__global__ void __launch_bounds__(128) k_bprep(const float* __restrict__ conv_b,
                                               const float* __restrict__ fc_W,
                                               const float* __restrict__ fc_b,
                                               float* __restrict__ fceff) {
    __shared__ float bs[DIM];
    int l = blockIdx.x, n = threadIdx.x;
    bs[n] = conv_b[(size_t)(l * 3 + 0) * DIM + n] + conv_b[(size_t)(l * 3 + 1) * DIM + n] +
            conv_b[(size_t)(l * 3 + 2) * DIM + n];
    __syncthreads();
    float acc = fc_b[(size_t)l * DIM + n];
    for (int k = 0; k < DIM; k++) acc += bs[k] * fc_W[(size_t)l * DIM * DIM + (size_t)k * DIM + n];
    fceff[(size_t)l * DIM + n] = acc;
}

// ---------------- fused gather (3 relations), fp16 m, relation-interleaved fast path ----------------
__global__ void __launch_bounds__(256) k_gather3(const __half* __restrict__ m0,
                                                 const __half* __restrict__ m1,
                                                 const __half* __restrict__ m2,
                                                 const int* __restrict__ srcidx,
                                                 const int* __restrict__ excl,
                                                 const int* __restrict__ cnt,
                                                 const float* __restrict__ dinv_i,
                                                 float* __restrict__ agg) {
    int node = (blockIdx.x * 256 + threadIdx.x) >> 5;
    int lane = threadIdx.x & 31;
    if (node >= NN) return;
    const __half* mr[3] = {m0, m1, m2};

    int n0 = cnt[node], n1 = cnt[NN + node], n2 = cnt[2 * NN + node];
    int b0 = excl[node], b1 = excl[NN + node], b2 = excl[2 * NN + node];

    float ax = 0.f, ay = 0.f, az = 0.f, aw = 0.f;

    if (n0 <= 32 && n1 <= 32 && n2 <= 32) {
        // ---- fast path: 3 index loads in flight, round-robin 4-edge batches across relations ----
        int i0 = (lane < n0) ? srcidx[b0 + lane] : 0;
        int i1 = (lane < n1) ? srcidx[b1 + lane] : 0;
        int i2 = (lane < n2) ? srcidx[b2 + lane] : 0;
        float S0x = 0.f, S0y = 0.f, S0z = 0.f, S0w = 0.f;
        float S1x = 0.f, S1y = 0.f, S1z = 0.f, S1w = 0.f;
        float S2x = 0.f, S2y = 0.f, S2z = 0.f, S2w = 0.f;
        int nmax = max(n0, max(n1, n2));
        for (int c = 0; c < nmax; c += 4) {
#pragma unroll
            for (int k = 0; k < 4; k++) {
                if (c + k < n0) {   // warp-uniform predicate
                    int s = __shfl_sync(~0u, i0, c + k);
                    uint2 u = *(const uint2*)(m0 + (size_t)s * DIM + lane * 4);
                    float2 a = __half22float2(*(__half2*)&u.x);
                    float2 b = __half22float2(*(__half2*)&u.y);
                    S0x += a.x; S0y += a.y; S0z += b.x; S0w += b.y;
                }
                if (c + k < n1) {
                    int s = __shfl_sync(~0u, i1, c + k);
                    uint2 u = *(const uint2*)(m1 + (size_t)s * DIM + lane * 4);
                    float2 a = __half22float2(*(__half2*)&u.x);
                    float2 b = __half22float2(*(__half2*)&u.y);
                    S1x += a.x; S1y += a.y; S1z += b.x; S1w += b.y;
                }
                if (c + k < n2) {
                    int s = __shfl_sync(~0u, i2, c + k);
                    uint2 u = *(const uint2*)(m2 + (size_t)s * DIM + lane * 4);
                    float2 a = __half22float2(*(__half2*)&u.x);
                    float2 b = __half22float2(*(__half2*)&u.y);
                    S2x += a.x; S2y += a.y; S2z += b.x; S2w += b.y;
                }
            }
        }
        float d0 = dinv_i[node], d1 = dinv_i[NN + node], d2 = dinv_i[2 * NN + node];
        ax = d0 * S0x + d1 * S1x + d2 * S2x;
        ay = d0 * S0y + d1 * S1y + d2 * S2y;
        az = d0 * S0z + d1 * S1z + d2 * S2z;
        aw = d0 * S0w + d1 * S1w + d2 * S2w;
    } else {
        // ---- generic path (rare): per-relation loop, 4-edge unroll ----
        int ns[3] = {n0, n1, n2};
        int bs[3] = {b0, b1, b2};
#pragma unroll
        for (int r = 0; r < NR; r++) {
            const __half* m = mr[r];
            int n = ns[r];
            int base = bs[r];
            float px = 0.f, py = 0.f, pz = 0.f, pw = 0.f;
            for (int c0 = 0; c0 < n; c0 += 32) {
                int sl = (c0 + lane < n) ? srcidx[base + c0 + lane] : 0;
                int lim = min(32, n - c0);
                for (int i = 0; i < lim; i++) {
                    int s0 = __shfl_sync(~0u, sl, i);
                    uint2 u0 = *(const uint2*)(m + (size_t)s0 * DIM + lane * 4);
                    float2 a0 = __half22float2(*(__half2*)&u0.x);
                    float2 b0v = __half22float2(*(__half2*)&u0.y);
                    px += a0.x; py += a0.y; pz += b0v.x; pw += b0v.y;
                }
            }
            float sc = dinv_i[r * NN + node];
            ax += sc * px; ay += sc * py; az += sc * pz; aw += sc * pw;
        }
    }
    *(float4*)(agg + (size_t)node * DIM + lane * 4) = make_float4(ax, ay, az, aw);
}

// ---------------- persistent SS-mode 3-relation conv GEMM (R14, unchanged) ----------------
#define G3_MB 8
#define G3_BNS 64
#define G3_BNB 576
#define G3_A 2048
#define G3_WH 67584
#define G3_WL 165888
#define G3_TOTAL 198656

template <bool BN>
__global__ void __launch_bounds__(256, 1) k_gemm3(const float4* __restrict__ A,
                                                  const uint8_t* __restrict__ Wimg,
                                                  const float* __restrict__ stats,
                                                  const float* __restrict__ gamma,
                                                  const float* __restrict__ beta,
                                                  const float* __restrict__ dinv_o,
                                                  __half* __restrict__ m0,
                                                  __half* __restrict__ m1,
                                                  __half* __restrict__ m2, int M) {
    extern __shared__ char sm[];
    int tid = threadIdx.x, wid = tid >> 5, lid = tid & 31;

#if HAS_TCGEN05
    uint32_t smb = smem_u32(sm);
    if (tid == 0) {
        MBARRIER_INIT(smb + G3_MB + 0, 1);
        MBARRIER_INIT(smb + G3_MB + 8, 1);
        MBARRIER_INIT(smb + G3_MB + 16, 1);
    }
    if (wid == 0) { TCGEN05_ALLOC(smb, 512); }

    float* bns = (float*)(sm + G3_BNS);
    float* bnb = (float*)(sm + G3_BNB);
    if (BN && tid < DIM) {
        float mean = stats[tid] * (1.f / NN);
        float var = stats[DIM + tid] * (1.f / NN) - mean * mean;
        float inv = rsqrtf(var + BN_EPS);
        float sc = gamma[tid] * inv;
        bns[tid] = sc;
        bnb[tid] = beta[tid] - mean * sc;
    }

    {
        float4* wh = (float4*)(sm + G3_WH);
        for (int i = tid; i < 6144; i += 256) {
            int r = i >> 11, j = i & 2047;
            wh[i] = ((const float4*)(Wimg + (size_t)r * 65536))[j];
        }
        float4* wl = (float4*)(sm + G3_WL);
        const float4* src = (const float4*)(Wimg + 32768);
        for (int i = tid; i < 2048; i += 256) wl[i] = src[i];
    }
    FENCE_ASYNC_SHARED();
    __syncthreads();

    uint32_t tmem;
    asm volatile("ld.shared.b32 %0, [%1];" : "=r"(tmem) : "r"(smb));
    bool issuer = (wid == 0) && elect_one();

    uint64_t aH = MAKE_SMEM_DESC(smb + G3_A);
    uint64_t aL = MAKE_SMEM_DESC(smb + G3_A + 32768);
    uint64_t bLo = MAKE_SMEM_DESC(smb + G3_WL);

    int rb = (wid & 3) * 32 + lid;
    int chalf = (wid >> 2) * 64;
    __half* mouts[3] = {m0, m1, m2};
    int par = 0;

    for (int tile = blockIdx.x; tile < MT; tile += gridDim.x) {
        int row0 = tile * 128;

#pragma unroll
        for (int g = 0; g < 2; g++) {
            float4 buf[8];
            int idx[8];
#pragma unroll
            for (int b = 0; b < 8; b++) {
                int i = g * 2048 + b * 256 + tid;
                idx[b] = i;
                int grow = row0 + (i >> 5);
                buf[b] = (grow < M) ? A[(size_t)grow * 32 + (i & 31)] : make_float4(0.f, 0.f, 0.f, 0.f);
            }
#pragma unroll
            for (int b = 0; b < 8; b++) {
                int i = idx[b];
                int row = i >> 5, c4 = i & 31;
                float4 v = buf[b];
                if (BN) {
                    int c = c4 * 4;
                    v.x = v.x * bns[c + 0] + bnb[c + 0];
                    v.y = v.y * bns[c + 1] + bnb[c + 1];
                    v.z = v.z * bns[c + 2] + bnb[c + 2];
                    v.w = v.w * bns[c + 3] + bnb[c + 3];
                }
                split_store(sm + G3_A, sm + G3_A + 32768, tile_off(row, c4 * 4), v);
            }
        }
        FENCE_ASYNC_SHARED();
        __syncthreads();

        if (issuer) {
            mma_pass3(tmem, aH, aL, MAKE_SMEM_DESC(smb + G3_WH), bLo);
            TCGEN05_COMMIT(smb + G3_MB + 0);
        }

#pragma unroll
        for (int r = 0; r < NR; r++) {
            mbar_wait(smb + G3_MB + 8 * r, par);
            TCGEN05_FENCE_AFTER();
            {
                int nxt = (r < 2) ? r + 1 : 0;
                const float4* src = (const float4*)(Wimg + (size_t)nxt * 65536 + 32768);
                float4* wl = (float4*)(sm + G3_WL);
#pragma unroll
                for (int q = 0; q < 8; q++) wl[tid + q * 256] = src[tid + q * 256];
            }
            FENCE_ASYNC_SHARED();
            __syncthreads();
            if (issuer && r < 2) {
                mma_pass3(tmem + (r + 1) * 128, aH, aL,
                          MAKE_SMEM_DESC(smb + G3_WH + (r + 1) * 32768), bLo);
                TCGEN05_COMMIT(smb + G3_MB + 8 * (r + 1));
            }
            int grow = row0 + rb;
            bool ok = grow < M;
            float rs = ok ? dinv_o[r * NN + grow] : 0.f;
            __half* op = mouts[r] + (size_t)grow * DIM;
#pragma unroll
            for (int hh = 0; hh < 2; hh++) {
                int cb = chalf + hh * 32;
                uint32_t dr[32];
                TCGEN05_LD_32X32B_X32(dr, tmem + r * 128 + cb);
                TCGEN05_WAIT_LD();
                if (ok) {
#pragma unroll
                    for (int j = 0; j < 8; j++) {
                        float4 c;
                        c.x = __uint_as_float(dr[4 * j + 0]) * rs;
                        c.y = __uint_as_float(dr[4 * j + 1]) * rs;
                        c.z = __uint_as_float(dr[4 * j + 2]) * rs;
                        c.w = __uint_as_float(dr[4 * j + 3]) * rs;
                        *(uint2*)(op + cb + 4 * j) = pack_half4(c);
                    }
                }
            }
        }
        __syncthreads();
        par ^= 1;
    }

    __syncthreads();
    if (wid == 0) TCGEN05_DEALLOC(tmem, 512);

#else  // fallback: persistent scalar
    float* Wf = (float*)sm;
    float* As = Wf + 16384;
    float* bns = As + 16 * 72;
    float* bnb = bns + DIM;

    if (BN && tid < DIM) {
        float mean = stats[tid] * (1.f / NN);
        float var = stats[DIM + tid] * (1.f / NN) - mean * mean;
        float inv = rsqrtf(var + BN_EPS);
        float sc = gamma[tid] * inv;
        bns[tid] = sc;
        bnb[tid] = beta[tid] - mean * sc;
    }
    __syncthreads();

    __half* mouts[3] = {m0, m1, m2};
    for (int tile = blockIdx.x; tile < MT; tile += gridDim.x) {
        int row0 = tile * 128;
        for (int r = 0; r < NR; r++) {
            for (int i = tid; i < 16384; i += 256) {
                int k = i >> 7, n = i & 127;
                uint32_t off = tile_off(n, k);
                const uint8_t* Wr = Wimg + (size_t)r * 65536;
                Wf[i] = __bfloat162float(*(const __nv_bfloat16*)(Wr + off)) +
                        __bfloat162float(*(const __nv_bfloat16*)(Wr + 32768 + off));
            }
            __syncthreads();

            int rbase = (tid >> 5) * 8;
            int cbase = (tid & 31) * 4;
            int arow = tid >> 2;
            int ak = (tid & 3) * 4;

            for (int halfb = 0; halfb < 2; halfb++) {
                int r0r = row0 + halfb * 64;
                int grow = r0r + arow;
                bool rowok = grow < M;
                const float4* Ar = A + (size_t)grow * 32;

                float acc[8][4];
#pragma unroll
                for (int i = 0; i < 8; i++)
#pragma unroll
                    for (int j = 0; j < 4; j++) acc[i][j] = 0.f;

                for (int kt = 0; kt < 8; ++kt) {
                    float4 av = rowok ? Ar[kt * 4 + (tid & 3)] : make_float4(0.f, 0.f, 0.f, 0.f);
                    if (BN) {
                        int c = kt * 16 + ak;
                        av.x = av.x * bns[c + 0] + bnb[c + 0];
                        av.y = av.y * bns[c + 1] + bnb[c + 1];
                        av.z = av.z * bns[c + 2] + bnb[c + 2];
                        av.w = av.w * bns[c + 3] + bnb[c + 3];
                    }
                    As[(ak + 0) * 72 + arow] = av.x;
                    As[(ak + 1) * 72 + arow] = av.y;
                    As[(ak + 2) * 72 + arow] = av.z;
                    As[(ak + 3) * 72 + arow] = av.w;
                    __syncthreads();
#pragma unroll
                    for (int kk = 0; kk < 16; ++kk) {
                        float4 b4 = *(float4*)&Wf[(kt * 16 + kk) * 128 + cbase];
                        float4 a0v = *(float4*)&As[kk * 72 + rbase];
                        float4 a1v = *(float4*)&As[kk * 72 + rbase + 4];
                        float a[8] = {a0v.x, a0v.y, a0v.z, a0v.w, a1v.x, a1v.y, a1v.z, a1v.w};
#pragma unroll
                        for (int i = 0; i < 8; i++) {
                            acc[i][0] += a[i] * b4.x;
                            acc[i][1] += a[i] * b4.y;
                            acc[i][2] += a[i] * b4.z;
                            acc[i][3] += a[i] * b4.w;
                        }
                    }
                    __syncthreads();
                }
#pragma unroll
                for (int i = 0; i < 8; i++) {
                    int rr = r0r + rbase + i;
                    if (rr < M) {
                        float rs = dinv_o[r * NN + rr];
                        float4 c;
                        c.x = acc[i][0] * rs; c.y = acc[i][1] * rs;
                        c.z = acc[i][2] * rs; c.w = acc[i][3] * rs;
                        *(uint2*)(mouts[r] + (size_t)rr * DIM + cbase) = pack_half4(c);
                    }
                }
            }
            __syncthreads();
        }
    }
#endif
}

// ---------------- FC GEMM (M=256 per CTA): C = relu(A @ W + bias) ----------------
#define SM_TMEM 0
#define SM_MBAR 8
#define SM_A 1024
#define SM_W (SM_A + 131072)
#define SM_TOTAL (SM_W + 65536)

__global__ void __launch_bounds__(256, 1) k_gemm_fc(const float4* __restrict__ A,
                                                    const uint8_t* __restrict__ Wimg,
                                                    const float* __restrict__ bias,
                                                    float* __restrict__ C, int M) {
    extern __shared__ char sm[];
    int tid = threadIdx.x, wid = tid >> 5, lid = tid & 31;
    int row0 = blockIdx.x * 256;

#if HAS_TCGEN05
    uint32_t smb = smem_u32(sm);
    if (tid == 0) MBARRIER_INIT(smb + SM_MBAR, 1);
    if (wid == 0) { TCGEN05_ALLOC(smb + SM_TMEM, 256); }
    __syncthreads();

    {
        const float4* Wv = (const float4*)Wimg;
        float4* Bv = (float4*)(sm + SM_W);
#pragma unroll
        for (int i = 0; i < 16; i++) Bv[tid + i * 256] = Wv[tid + i * 256];
    }

#pragma unroll
    for (int g = 0; g < 4; g++) {
        float4 buf[8];
        int idx[8];
#pragma unroll
        for (int b = 0; b < 8; b++) {
            int i = g * 2048 + b * 256 + tid;
            idx[b] = i;
            int grow = row0 + (i >> 5);
            buf[b] = (grow < M) ? A[(size_t)grow * 32 + (i & 31)] : make_float4(0.f, 0.f, 0.f, 0.f);
        }
#pragma unroll
        for (int b = 0; b < 8; b++) {
            int i = idx[b];
            int row = i >> 5, c4 = i & 31;
            int t = row >> 7, lrow = row & 127;
            split_store(sm + SM_A + t * 65536, sm + SM_A + t * 65536 + 32768,
                        tile_off(lrow, c4 * 4), buf[b]);
        }
    }

    FENCE_ASYNC_SHARED();
    __syncthreads();

    uint32_t tmem;
    asm volatile("ld.shared.b32 %0, [%1];" : "=r"(tmem) : "r"(smb + SM_TMEM));

    if (wid == 0 && elect_one()) {
        uint64_t bH = MAKE_SMEM_DESC(smb + SM_W);
        uint64_t bL = MAKE_SMEM_DESC(smb + SM_W + 32768);
#pragma unroll
        for (int t = 0; t < 2; t++) {
            uint64_t aH = MAKE_SMEM_DESC(smb + SM_A + t * 65536);
            uint64_t aL = MAKE_SMEM_DESC(smb + SM_A + t * 65536 + 32768);
            mma_pass3(tmem + t * 128, aH, aL, bH, bL);
        }
        TCGEN05_COMMIT(smb + SM_MBAR);
    }

    mbar_wait(smb + SM_MBAR, 0);
    TCGEN05_FENCE_AFTER();

#pragma unroll
    for (int t = 0; t < 2; t++) {
        int rb = t * 128 + (wid & 3) * 32 + lid;
        int grow = row0 + rb;
        int chalf = (wid >> 2) * 64;
#pragma unroll
        for (int hh = 0; hh < 2; hh++) {
            int cb = chalf + hh * 32;
            uint32_t dr[32];
            TCGEN05_LD_32X32B_X32(dr, tmem + t * 128 + cb);
            TCGEN05_WAIT_LD();
            if (grow < M) {
                float* op = C + (size_t)grow * DIM + cb;
#pragma unroll
                for (int j = 0; j < 8; j++) {
                    float4 bv = *(const float4*)(bias + cb + 4 * j);
                    float4 c;
                    c.x = fmaxf(__uint_as_float(dr[4 * j + 0]) + bv.x, 0.f);
                    c.y = fmaxf(__uint_as_float(dr[4 * j + 1]) + bv.y, 0.f);
                    c.z = fmaxf(__uint_as_float(dr[4 * j + 2]) + bv.z, 0.f);
                    c.w = fmaxf(__uint_as_float(dr[4 * j + 3]) + bv.w, 0.f);
                    *(float4*)(op + 4 * j) = c;
                }
            }
        }
    }

    __syncthreads();
    if (wid == 0) TCGEN05_DEALLOC(tmem, 256);

#else  // fallback
    float* Wf = (float*)sm;
    float* As = Wf + 16384;

    for (int i = tid; i < 16384; i += 256) {
        int k = i >> 7, n = i & 127;
        uint32_t off = tile_off(n, k);
        Wf[i] = __bfloat162float(*(const __nv_bfloat16*)(Wimg + off)) +
                __bfloat162float(*(const __nv_bfloat16*)(Wimg + 32768 + off));
    }
    __syncthreads();

    int rbase = (tid >> 5) * 8;
    int cbase = (tid & 31) * 4;
    int arow = tid >> 2;
    int ak = (tid & 3) * 4;

    for (int half = 0; half < 4; half++) {
        int r0 = row0 + half * 64;
        int grow = r0 + arow;
        bool rowok = grow < M;
        const float4* Ar = A + (size_t)grow * 32;

        float acc[8][4];
#pragma unroll
        for (int i = 0; i < 8; i++)
#pragma unroll
            for (int j = 0; j < 4; j++) acc[i][j] = 0.f;

        for (int kt = 0; kt < 8; ++kt) {
            float4 av = rowok ? Ar[kt * 4 + (tid & 3)] : make_float4(0.f, 0.f, 0.f, 0.f);
            As[(ak + 0) * 72 + arow] = av.x;
            As[(ak + 1) * 72 + arow] = av.y;
            As[(ak + 2) * 72 + arow] = av.z;
            As[(ak + 3) * 72 + arow] = av.w;
            __syncthreads();
#pragma unroll
            for (int kk = 0; kk < 16; ++kk) {
                float4 b4 = *(float4*)&Wf[(kt * 16 + kk) * 128 + cbase];
                float4 a0v = *(float4*)&As[kk * 72 + rbase];
                float4 a1v = *(float4*)&As[kk * 72 + rbase + 4];
                float a[8] = {a0v.x, a0v.y, a0v.z, a0v.w, a1v.x, a1v.y, a1v.z, a1v.w};
#pragma unroll
                for (int i = 0; i < 8; i++) {
                    acc[i][0] += a[i] * b4.x;
                    acc[i][1] += a[i] * b4.y;
                    acc[i][2] += a[i] * b4.z;
                    acc[i][3] += a[i] * b4.w;
                }
            }
            __syncthreads();
        }

        float4 bv = *(const float4*)(bias + cbase);
#pragma unroll
        for (int i = 0; i < 8; i++) {
            int r = r0 + rbase + i;
            if (r < M) {
                float4 c;
                c.x = fmaxf(acc[i][0] + bv.x, 0.f);
                c.y = fmaxf(acc[i][1] + bv.y, 0.f);
                c.z = fmaxf(acc[i][2] + bv.z, 0.f);
                c.w = fmaxf(acc[i][3] + bv.w, 0.f);
                *(float4*)(C + (size_t)r * DIM + cbase) = c;
            }
        }
    }
#endif
}

// ---------------- BatchNorm ----------------
__global__ void __launch_bounds__(128) k_bnstats(const float* __restrict__ h, float* __restrict__ stats) {
    int c = threadIdx.x;
    float s = 0.f, s2 = 0.f;
    for (int r = blockIdx.x; r < NN; r += gridDim.x) {
        float v = h[(size_t)r * DIM + c];
        s += v;
        s2 += v * v;
    }
    atomicAdd(&stats[c], s);
    atomicAdd(&stats[DIM + c], s2);
}
__global__ void __launch_bounds__(256) k_bnnorm(const float* __restrict__ h,
                                                const float* __restrict__ stats,
                                                const float* __restrict__ gamma,
                                                const float* __restrict__ beta,
                                                float* __restrict__ out) {
    int i = blockIdx.x * 256 + threadIdx.x;
    if (i >= NN * DIM / 4) return;
    int c = (i & 31) * 4;
    float4 v = *(const float4*)(h + (size_t)i * 4);
    float vin[4] = {v.x, v.y, v.z, v.w};
    float o[4];
#pragma unroll
    for (int j = 0; j < 4; j++) {
        float mean = stats[c + j] * (1.f / NN);
        float var = stats[DIM + c + j] * (1.f / NN) - mean * mean;
        float inv = rsqrtf(var + BN_EPS);
        o[j] = (vin[j] - mean) * inv * gamma[c + j] + beta[c + j];
    }
    *(float4*)(out + (size_t)i * 4) = make_float4(o[0], o[1], o[2], o[3]);
}

// ---------------- launch ----------------
extern "C" void kernel_launch(void* const* d_in, const int* in_sizes, int n_in,
                              void* d_out, int out_size) {
    const float* x      = (const float*)d_in[0];
    const int*   edges  = (const int*)d_in[1];
    const float* conv_W = (const float*)d_in[2];
    const float* conv_b = (const float*)d_in[3];
    const float* fc_W   = (const float*)d_in[4];
    const float* fc_b   = (const float*)d_in[5];
    const float* gamma  = (const float*)d_in[6];
    const float* beta   = (const float*)d_in[7];
    float* out = (float*)d_out;

    float *h, *agg, *dinv_o, *dinv_i, *stats3, *fceff;
    __half *m0, *m1, *m2;
    int *cnt_in, *cnt_out, *cursor, *excl, *bsum, *srcidx;
    uint8_t* wbf;
    cudaGetSymbolAddress((void**)&h, g_h);
    cudaGetSymbolAddress((void**)&m0, g_m0);
    cudaGetSymbolAddress((void**)&m1, g_m1);
    cudaGetSymbolAddress((void**)&m2, g_m2);
    cudaGetSymbolAddress((void**)&agg, g_agg);
    cudaGetSymbolAddress((void**)&dinv_o, g_dinv_o);
    cudaGetSymbolAddress((void**)&dinv_i, g_dinv_i);
    cudaGetSymbolAddress((void**)&cnt_in, g_cnt_in);
    cudaGetSymbolAddress((void**)&cnt_out, g_cnt_out);
    cudaGetSymbolAddress((void**)&cursor, g_cursor);
    cudaGetSymbolAddress((void**)&excl, g_excl);
    cudaGetSymbolAddress((void**)&bsum, g_bsum);
    cudaGetSymbolAddress((void**)&srcidx, g_srcidx);
    cudaGetSymbolAddress((void**)&stats3, g_stats3);
    cudaGetSymbolAddress((void**)&wbf, g_Wbf);
    cudaGetSymbolAddress((void**)&fceff, g_fceff);

    cudaFuncSetAttribute(k_gemm3<false>, cudaFuncAttributeMaxDynamicSharedMemorySize, G3_TOTAL);
    cudaFuncSetAttribute(k_gemm3<true>, cudaFuncAttributeMaxDynamicSharedMemorySize, G3_TOTAL);
    cudaFuncSetAttribute(k_gemm_fc, cudaFuncAttributeMaxDynamicSharedMemorySize, SM_TOTAL);

    const int nh4 = NN * DIM / 4;
    const int NSC = NR * NN;
    const int NB1 = (NSC + 1023) / 1024;

    // ---- prep ----
    k_wprep<<<(12 * 16384 + 255) / 256, 256>>>(conv_W, fc_W, wbf);
    k_bprep<<<NL, 128>>>(conv_b, fc_W, fc_b, fceff);
    k_zeroprep<<<(NSC + 255) / 256, 256>>>(cnt_in, cnt_out, cursor, stats3, NSC);
    k_cnt<<<(NR * NE + 255) / 256, 256>>>(edges, cnt_out, cnt_in);
    k_dinv<<<(NSC + 255) / 256, 256>>>(cnt_out, cnt_in, dinv_o, dinv_i);
    k_scan1<<<NB1, 1024>>>(cnt_in, excl, bsum, NSC);
    k_scan2<<<1, 512>>>(bsum, NB1);
    k_scan3<<<NB1, 1024>>>(excl, bsum, NSC);
    k_place<<<(NR * NE + 255) / 256, 256>>>(edges, excl, cursor, srcidx);

    const int GGRID = (NN * 32 + 255) / 256;
    const int FCGRID = (NN + 255) / 256;     // 391

    for (int l = 0; l < NL; ++l) {
        if (l == 0)
            k_gemm3<false><<<148, 256, G3_TOTAL>>>(
                (const float4*)x, wbf + (size_t)(l * NR) * 65536,
                nullptr, nullptr, nullptr, dinv_o, m0, m1, m2, NN);
        else
            k_gemm3<true><<<148, 256, G3_TOTAL>>>(
                (const float4*)h, wbf + (size_t)(l * NR) * 65536,
                stats3 + (size_t)(l - 1) * 2 * DIM,
                gamma + (size_t)(l - 1) * DIM, beta + (size_t)(l - 1) * DIM,
                dinv_o, m0, m1, m2, NN);
        k_gather3<<<GGRID, 256>>>(m0, m1, m2, srcidx, excl, cnt_in, dinv_i, agg);
        k_gemm_fc<<<FCGRID, 256, SM_TOTAL>>>((const float4*)agg,
                                             wbf + (size_t)(9 + l) * 65536,
                                             fceff + (size_t)l * DIM, h, NN);
        k_bnstats<<<1024, 128>>>(h, stats3 + (size_t)l * 2 * DIM);
    }
    k_bnnorm<<<(nh4 + 255) / 256, 256>>>(h, stats3 + (size_t)(NL - 1) * 2 * DIM,
                                         gamma + (size_t)(NL - 1) * DIM,
                                         beta + (size_t)(NL - 1) * DIM, out);
}

// round 16
// speedup vs baseline: 1.1493x; 1.1493x over previous
#include <cuda_runtime.h>
#include <cuda_bf16.h>
#include <cuda_fp16.h>
#include <cstdint>

#define NN 100000
#define NE 600000
#define NR 3
#define NL 3
#define DIM 128
#define BN_EPS 1e-5f
#define MT ((NN + 127) / 128)   // 782 tiles

#if defined(__CUDA_ARCH_FEAT_SM103_ALL) || defined(__CUDA_ARCH_FEAT_SM100_ALL) || \
    defined(__CUDA_ARCH_FEAT_SM101_ALL) || \
    (defined(__CUDA_ARCH_FAMILY_SPECIFIC__) && (__CUDA_ARCH_FAMILY_SPECIFIC__ >= 1000)) || \
    (defined(__CUDA_ARCH_SPECIFIC__) && (__CUDA_ARCH_SPECIFIC__ >= 1000))
#define HAS_TCGEN05 1
#else
#define HAS_TCGEN05 0
#endif

// ---------------- scratch ----------------
__device__ __align__(16) float g_h[(size_t)NN * DIM];
__device__ __align__(16) __half g_m0[(size_t)NN * DIM];
__device__ __align__(16) __half g_m1[(size_t)NN * DIM];
__device__ __align__(16) __half g_m2[(size_t)NN * DIM];
__device__ __align__(16) float g_agg[(size_t)NN * DIM];
__device__ __align__(16) float g_dinv_o[NR * NN];
__device__ __align__(16) float g_dinv_i[NR * NN];
__device__ __align__(16) int g_cnt_in[NR * NN];
__device__ __align__(16) int g_cnt_out[NR * NN];
__device__ __align__(16) int g_cursor[NR * NN];
__device__ __align__(16) int g_excl[NR * NN];
__device__ __align__(16) int g_bsum[512];
__device__ __align__(16) int g_srcidx[NR * NE];
__device__ __align__(16) float g_stats3[NL * 2 * DIM];
__device__ __align__(16) uint8_t g_Wbf[12 * 65536];
__device__ __align__(16) float g_fceff[NL * DIM];

// ---------------- PTX helpers ----------------
__device__ __forceinline__ uint32_t smem_u32(const void* p) {
    uint32_t a;
    asm("{ .reg .u64 t; cvta.to.shared.u64 t, %1; cvt.u32.u64 %0, t; }" : "=r"(a) : "l"(p));
    return a;
}

#if HAS_TCGEN05
__device__ __forceinline__ uint32_t elect_one() {
    uint32_t pred;
    asm volatile("{\n\t.reg .pred p;\n\telect.sync _|p, 0xFFFFFFFF;\n\tselp.b32 %0, 1, 0, p;\n\t}" : "=r"(pred));
    return pred;
}
#define MBARRIER_INIT(addr, cnt) \
    asm volatile("mbarrier.init.shared.b64 [%0], %1;" :: "r"((uint32_t)(addr)), "r"((uint32_t)(cnt)) : "memory")
__device__ __forceinline__ void mbar_wait(uint32_t mbar, uint32_t parity) {
    asm volatile(
        "{\n\t.reg .pred P;\n\t"
        "WL_%=:\n\t"
        "mbarrier.try_wait.parity.acquire.cta.shared::cta.b64 P, [%0], %1, 0x989680;\n\t"
        "@P bra.uni WD_%=;\n\t"
        "bra.uni WL_%=;\n\t"
        "WD_%=:\n\t}"
        :: "r"(mbar), "r"(parity) : "memory");
}
#define TCGEN05_ALLOC(smem_addr, n) \
    asm volatile("tcgen05.alloc.cta_group::1.sync.aligned.shared::cta.b32 [%0], %1;" \
                 :: "r"((uint32_t)(smem_addr)), "r"((uint32_t)(n)) : "memory")
#define TCGEN05_DEALLOC(tmem, n) \
    asm volatile("tcgen05.dealloc.cta_group::1.sync.aligned.b32 %0, %1;" :: "r"(tmem), "r"((uint32_t)(n)))
#define TCGEN05_COMMIT(mbar) \
    asm volatile("tcgen05.commit.cta_group::1.mbarrier::arrive::one.shared::cluster.b64 [%0];" \
                 :: "r"((uint32_t)(mbar)) : "memory")
#define TCGEN05_WAIT_LD() asm volatile("tcgen05.wait::ld.sync.aligned;" ::: "memory")
#define TCGEN05_FENCE_AFTER() asm volatile("tcgen05.fence::after_thread_sync;" ::: "memory")
#define FENCE_ASYNC_SHARED() asm volatile("fence.proxy.async.shared::cta;" ::: "memory")

#define TCGEN05_LD_32X32B_X32(r, tmem_addr) \
    asm volatile( \
        "tcgen05.ld.sync.aligned.32x32b.x32.b32 " \
        "{%0, %1, %2, %3, %4, %5, %6, %7, " \
        " %8, %9, %10, %11, %12, %13, %14, %15, " \
        " %16, %17, %18, %19, %20, %21, %22, %23, " \
        " %24, %25, %26, %27, %28, %29, %30, %31}, [%32];" \
        : "=r"((r)[0]),  "=r"((r)[1]),  "=r"((r)[2]),  "=r"((r)[3]), \
          "=r"((r)[4]),  "=r"((r)[5]),  "=r"((r)[6]),  "=r"((r)[7]), \
          "=r"((r)[8]),  "=r"((r)[9]),  "=r"((r)[10]), "=r"((r)[11]), \
          "=r"((r)[12]), "=r"((r)[13]), "=r"((r)[14]), "=r"((r)[15]), \
          "=r"((r)[16]), "=r"((r)[17]), "=r"((r)[18]), "=r"((r)[19]), \
          "=r"((r)[20]), "=r"((r)[21]), "=r"((r)[22]), "=r"((r)[23]), \
          "=r"((r)[24]), "=r"((r)[25]), "=r"((r)[26]), "=r"((r)[27]), \
          "=r"((r)[28]), "=r"((r)[29]), "=r"((r)[30]), "=r"((r)[31]) \
        : "r"(tmem_addr))

static constexpr uint64_t SMEM_DESC_BASE_SW128 =
    (uint64_t(2) << 61) | (uint64_t(1) << 46) | (uint64_t(64) << 32) | (uint64_t(1) << 16);
#define MAKE_SMEM_DESC(base_addr) (SMEM_DESC_BASE_SW128 | ((uint64_t)((base_addr) >> 4) & 0x3FFF))

__device__ __forceinline__ void mma_f16_ss(uint32_t d, uint64_t a, uint64_t b, uint32_t idesc, int acc) {
    asm volatile(
        "{\n\t.reg .pred p;\n\tsetp.ne.u32 p, %4, 0;\n\t"
        "tcgen05.mma.cta_group::1.kind::f16 [%0], %1, %2, %3, {%5, %5, %5, %5}, p;\n\t}"
        :: "r"(d), "l"(a), "l"(b), "r"(idesc), "r"(acc), "r"(0u) : "memory");
}
#define MMA_IDESC 0x8200490u

// 3-pass hi/lo sweep: AhBh + AhBl + AlBh
__device__ __forceinline__ void mma_pass3(uint32_t d, uint64_t aH, uint64_t aL, uint64_t bH, uint64_t bL) {
    uint64_t ad[3] = {aH, aH, aL};
    uint64_t bd[3] = {bH, bL, bH};
#pragma unroll
    for (int p = 0; p < 3; p++)
#pragma unroll
        for (int s = 0; s < 8; s++) {
            uint64_t o = (s < 4) ? (uint64_t)(s * 2) : (uint64_t)(1024 + (s - 4) * 2);
            mma_f16_ss(d, ad[p] + o, bd[p] + o, MMA_IDESC, !(p == 0 && s == 0));
        }
}
#endif  // HAS_TCGEN05

// Blocked SW128 atom layout for a 128x128 bf16 tile.
__host__ __device__ __forceinline__ uint32_t tile_off(int row, int col) {
    uint32_t off = (uint32_t)(((row >> 3) + ((col >> 6) << 4)) << 10) | ((row & 7) << 7) | ((col & 63) << 1);
    return off ^ ((off >> 3) & 0x70);
}

__device__ __forceinline__ void split_store(char* base_hi, char* base_lo, uint32_t off, float4 v) {
    __nv_bfloat162 h01 = __floats2bfloat162_rn(v.x, v.y);
    __nv_bfloat162 h23 = __floats2bfloat162_rn(v.z, v.w);
    float lx = v.x - __bfloat162float(h01.x);
    float ly = v.y - __bfloat162float(h01.y);
    float lz = v.z - __bfloat162float(h23.x);
    float lw = v.w - __bfloat162float(h23.y);
    __nv_bfloat162 l01 = __floats2bfloat162_rn(lx, ly);
    __nv_bfloat162 l23 = __floats2bfloat162_rn(lz, lw);
    uint2 hv, lv;
    hv.x = *(uint32_t*)&h01; hv.y = *(uint32_t*)&h23;
    lv.x = *(uint32_t*)&l01; lv.y = *(uint32_t*)&l23;
    *(uint2*)(base_hi + off) = hv;
    *(uint2*)(base_lo + off) = lv;
}

__device__ __forceinline__ uint2 pack_half4(float4 v) {
    __half2 p0 = __floats2half2_rn(v.x, v.y);
    __half2 p1 = __floats2half2_rn(v.z, v.w);
    uint2 u;
    u.x = *(uint32_t*)&p0;
    u.y = *(uint32_t*)&p1;
    return u;
}

// ---------------- prep kernels ----------------
__global__ void __launch_bounds__(256) k_zeroprep(int* a, int* b, int* c, float* stats, int n) {
    int i = blockIdx.x * 256 + threadIdx.x;
    if (i < n) { a[i] = 0; b[i] = 0; c[i] = 0; }
    if (i < NL * 2 * DIM) stats[i] = 0.f;
}
__global__ void __launch_bounds__(256) k_cnt(const int* __restrict__ edges,
                                             int* __restrict__ cnt_out, int* __restrict__ cnt_in) {
    int i = blockIdx.x * 256 + threadIdx.x;
    if (i >= NR * NE) return;
    int r = i / NE;
    int e = i - r * NE;
    int s = edges[(size_t)(r * 2 + 0) * NE + e];
    int d = edges[(size_t)(r * 2 + 1) * NE + e];
    atomicAdd(&cnt_out[r * NN + s], 1);
    atomicAdd(&cnt_in[r * NN + d], 1);
}
__global__ void __launch_bounds__(256) k_dinv(const int* __restrict__ cnt_out, const int* __restrict__ cnt_in,
                                              float* __restrict__ dinv_o, float* __restrict__ dinv_i) {
    int i = blockIdx.x * 256 + threadIdx.x;
    if (i >= NR * NN) return;
    dinv_o[i] = rsqrtf(fmaxf((float)cnt_out[i], 1.f));
    dinv_i[i] = rsqrtf(fmaxf((float)cnt_in[i], 1.f));
}
__global__ void __launch_bounds__(1024) k_scan1(const int* __restrict__ cnt, int* __restrict__ excl,
                                                int* __restrict__ bsum, int N) {
    int i = blockIdx.x * 1024 + threadIdx.x;
    int lane = threadIdx.x & 31, warp = threadIdx.x >> 5;
    int x = (i < N) ? cnt[i] : 0;
    int v = x;
#pragma unroll
    for (int o = 1; o < 32; o <<= 1) { int y = __shfl_up_sync(~0u, v, o); if (lane >= o) v += y; }
    __shared__ int ws[32];
    if (lane == 31) ws[warp] = v;
    __syncthreads();
    if (warp == 0) {
        int w = ws[lane];
#pragma unroll
        for (int o = 1; o < 32; o <<= 1) { int y = __shfl_up_sync(~0u, w, o); if (lane >= o) w += y; }
        ws[lane] = w;
    }
    __syncthreads();
    int wexcl = (warp == 0) ? 0 : ws[warp - 1];
    if (i < N) excl[i] = wexcl + v - x;
    if (threadIdx.x == 1023) bsum[blockIdx.x] = ws[31];
}
__global__ void __launch_bounds__(512) k_scan2(int* __restrict__ bsum, int nb) {
    __shared__ int s[512];
    int tid = threadIdx.x;
    int v = (tid < nb) ? bsum[tid] : 0;
    s[tid] = v;
    __syncthreads();
    for (int o = 1; o < 512; o <<= 1) {
        int y = (tid >= o) ? s[tid - o] : 0;
        __syncthreads();
        s[tid] += y;
        __syncthreads();
    }
    if (tid < nb) bsum[tid] = s[tid] - v;
}
__global__ void __launch_bounds__(1024) k_scan3(int* __restrict__ excl, const int* __restrict__ bsum, int N) {
    int i = blockIdx.x * 1024 + threadIdx.x;
    if (i < N) excl[i] += bsum[blockIdx.x];
}
__global__ void __launch_bounds__(256) k_place(const int* __restrict__ edges, const int* __restrict__ excl,
                                               int* __restrict__ cursor, int* __restrict__ srcidx) {
    int i = blockIdx.x * 256 + threadIdx.x;
    if (i >= NR * NE) return;
    int r = i / NE;
    int e = i - r * NE;
    int s = edges[(size_t)(r * 2 + 0) * NE + e];
    int d = edges[(size_t)(r * 2 + 1) * NE + e];
    int pos = atomicAdd(&cursor[r * NN + d], 1);
    srcidx[excl[r * NN + d] + pos] = s;
}
__global__ void __launch_bounds__(256) k_wprep(const float* __restrict__ convW,
                                               const float* __restrict__ fcW,
                                               uint8_t* __restrict__ wbf) {
    int idx = blockIdx.x * 256 + threadIdx.x;
    if (idx >= 12 * 16384) return;
    int w = idx >> 14;
    int e = idx & 16383;
    int k = e >> 7, n = e & 127;
    const float* W = (w < 9) ? (convW + (size_t)w * 16384) : (fcW + (size_t)(w - 9) * 16384);
    float v = W[e];
    __nv_bfloat16 hi = __float2bfloat16(v);
    __nv_bfloat16 lo = __float2bfloat16(v - __bfloat162float(hi));
    uint32_t off = tile_off(n, k);
    *(__nv_bfloat16*)(wbf + (size_t)w * 65536 + off) = hi;
    *(__nv_bfloat16*)(wbf + (size_t)w * 65536 + 32768 + off) = lo;
}
__global__ void __launch_bounds__(128) k_bprep(const float* __restrict__ conv_b,
                                               const float* __restrict__ fc_W,
                                               const float* __restrict__ fc_b,
                                               float* __restrict__ fceff) {
    __shared__ float bs[DIM];
    int l = blockIdx.x, n = threadIdx.x;
    bs[n] = conv_b[(size_t)(l * 3 + 0) * DIM + n] + conv_b[(size_t)(l * 3 + 1) * DIM + n] +
            conv_b[(size_t)(l * 3 + 2) * DIM + n];
    __syncthreads();
    float acc = fc_b[(size_t)l * DIM + n];
    for (int k = 0; k < DIM; k++) acc += bs[k] * fc_W[(size_t)l * DIM * DIM + (size_t)k * DIM + n];
    fceff[(size_t)l * DIM + n] = acc;
}

// ---------------- fused gather (3 relations), fp16 m, 4-edge unroll ----------------
__global__ void __launch_bounds__(256) k_gather3(const __half* __restrict__ m0,
                                                 const __half* __restrict__ m1,
                                                 const __half* __restrict__ m2,
                                                 const int* __restrict__ srcidx,
                                                 const int* __restrict__ excl,
                                                 const int* __restrict__ cnt,
                                                 const float* __restrict__ dinv_i,
                                                 float* __restrict__ agg) {
    int node = (blockIdx.x * 256 + threadIdx.x) >> 5;
    int lane = threadIdx.x & 31;
    if (node >= NN) return;
    const __half* mr[3] = {m0, m1, m2};
    float ax = 0.f, ay = 0.f, az = 0.f, aw = 0.f;
#pragma unroll
    for (int r = 0; r < NR; r++) {
        const __half* m = mr[r];
        int n = cnt[r * NN + node];
        int base = excl[r * NN + node];
        float px = 0.f, py = 0.f, pz = 0.f, pw = 0.f;
        for (int c0 = 0; c0 < n; c0 += 32) {
            int sl = (c0 + lane < n) ? srcidx[base + c0 + lane] : 0;
            int lim = min(32, n - c0);
            int i = 0;
            for (; i + 3 < lim; i += 4) {
                int s0 = __shfl_sync(~0u, sl, i);
                int s1 = __shfl_sync(~0u, sl, i + 1);
                int s2 = __shfl_sync(~0u, sl, i + 2);
                int s3 = __shfl_sync(~0u, sl, i + 3);
                uint2 u0 = *(const uint2*)(m + (size_t)s0 * DIM + lane * 4);
                uint2 u1 = *(const uint2*)(m + (size_t)s1 * DIM + lane * 4);
                uint2 u2 = *(const uint2*)(m + (size_t)s2 * DIM + lane * 4);
                uint2 u3 = *(const uint2*)(m + (size_t)s3 * DIM + lane * 4);
                float2 a0 = __half22float2(*(__half2*)&u0.x);
                float2 b0 = __half22float2(*(__half2*)&u0.y);
                float2 a1 = __half22float2(*(__half2*)&u1.x);
                float2 b1 = __half22float2(*(__half2*)&u1.y);
                float2 a2 = __half22float2(*(__half2*)&u2.x);
                float2 b2 = __half22float2(*(__half2*)&u2.y);
                float2 a3 = __half22float2(*(__half2*)&u3.x);
                float2 b3 = __half22float2(*(__half2*)&u3.y);
                px += (a0.x + a1.x) + (a2.x + a3.x);
                py += (a0.y + a1.y) + (a2.y + a3.y);
                pz += (b0.x + b1.x) + (b2.x + b3.x);
                pw += (b0.y + b1.y) + (b2.y + b3.y);
            }
            for (; i < lim; i++) {
                int s0 = __shfl_sync(~0u, sl, i);
                uint2 u0 = *(const uint2*)(m + (size_t)s0 * DIM + lane * 4);
                float2 a0 = __half22float2(*(__half2*)&u0.x);
                float2 b0 = __half22float2(*(__half2*)&u0.y);
                px += a0.x; py += a0.y; pz += b0.x; pw += b0.y;
            }
        }
        float sc = dinv_i[r * NN + node];
        ax += sc * px; ay += sc * py; az += sc * pz; aw += sc * pw;
    }
    *(float4*)(agg + (size_t)node * DIM + lane * 4) = make_float4(ax, ay, az, aw);
}

// ---------------- persistent SS-mode 3-relation conv GEMM ----------------
// Grid=148. Resident: W-hi x3 (96KB) + A hi/lo (64KB). W-lo streamed via one 32KB buffer.
#define G3_MB 8
#define G3_BNS 64
#define G3_BNB 576
#define G3_A 2048
#define G3_WH 67584
#define G3_WL 165888
#define G3_TOTAL 198656

template <bool BN>
__global__ void __launch_bounds__(256, 1) k_gemm3(const float4* __restrict__ A,
                                                  const uint8_t* __restrict__ Wimg,
                                                  const float* __restrict__ stats,
                                                  const float* __restrict__ gamma,
                                                  const float* __restrict__ beta,
                                                  const float* __restrict__ dinv_o,
                                                  __half* __restrict__ m0,
                                                  __half* __restrict__ m1,
                                                  __half* __restrict__ m2, int M) {
    extern __shared__ char sm[];
    int tid = threadIdx.x, wid = tid >> 5, lid = tid & 31;

#if HAS_TCGEN05
    uint32_t smb = smem_u32(sm);
    if (tid == 0) {
        MBARRIER_INIT(smb + G3_MB + 0, 1);
        MBARRIER_INIT(smb + G3_MB + 8, 1);
        MBARRIER_INIT(smb + G3_MB + 16, 1);
    }
    if (wid == 0) { TCGEN05_ALLOC(smb, 512); }

    float* bns = (float*)(sm + G3_BNS);
    float* bnb = (float*)(sm + G3_BNB);
    if (BN && tid < DIM) {
        float mean = stats[tid] * (1.f / NN);
        float var = stats[DIM + tid] * (1.f / NN) - mean * mean;
        float inv = rsqrtf(var + BN_EPS);
        float sc = gamma[tid] * inv;
        bns[tid] = sc;
        bnb[tid] = beta[tid] - mean * sc;
    }

    {
        float4* wh = (float4*)(sm + G3_WH);
        for (int i = tid; i < 6144; i += 256) {
            int r = i >> 11, j = i & 2047;
            wh[i] = ((const float4*)(Wimg + (size_t)r * 65536))[j];
        }
        float4* wl = (float4*)(sm + G3_WL);
        const float4* src = (const float4*)(Wimg + 32768);
        for (int i = tid; i < 2048; i += 256) wl[i] = src[i];
    }
    FENCE_ASYNC_SHARED();
    __syncthreads();

    uint32_t tmem;
    asm volatile("ld.shared.b32 %0, [%1];" : "=r"(tmem) : "r"(smb));
    bool issuer = (wid == 0) && elect_one();

    uint64_t aH = MAKE_SMEM_DESC(smb + G3_A);
    uint64_t aL = MAKE_SMEM_DESC(smb + G3_A + 32768);
    uint64_t bLo = MAKE_SMEM_DESC(smb + G3_WL);

    int rb = (wid & 3) * 32 + lid;
    int chalf = (wid >> 2) * 64;
    __half* mouts[3] = {m0, m1, m2};
    int par = 0;

    for (int tile = blockIdx.x; tile < MT; tile += gridDim.x) {
        int row0 = tile * 128;

#pragma unroll
        for (int g = 0; g < 2; g++) {
            float4 buf[8];
            int idx[8];
#pragma unroll
            for (int b = 0; b < 8; b++) {
                int i = g * 2048 + b * 256 + tid;
                idx[b] = i;
                int grow = row0 + (i >> 5);
                buf[b] = (grow < M) ? A[(size_t)grow * 32 + (i & 31)] : make_float4(0.f, 0.f, 0.f, 0.f);
            }
#pragma unroll
            for (int b = 0; b < 8; b++) {
                int i = idx[b];
                int row = i >> 5, c4 = i & 31;
                float4 v = buf[b];
                if (BN) {
                    int c = c4 * 4;
                    v.x = v.x * bns[c + 0] + bnb[c + 0];
                    v.y = v.y * bns[c + 1] + bnb[c + 1];
                    v.z = v.z * bns[c + 2] + bnb[c + 2];
                    v.w = v.w * bns[c + 3] + bnb[c + 3];
                }
                split_store(sm + G3_A, sm + G3_A + 32768, tile_off(row, c4 * 4), v);
            }
        }
        FENCE_ASYNC_SHARED();
        __syncthreads();

        if (issuer) {
            mma_pass3(tmem, aH, aL, MAKE_SMEM_DESC(smb + G3_WH), bLo);
            TCGEN05_COMMIT(smb + G3_MB + 0);
        }

#pragma unroll
        for (int r = 0; r < NR; r++) {
            mbar_wait(smb + G3_MB + 8 * r, par);
            TCGEN05_FENCE_AFTER();
            {
                int nxt = (r < 2) ? r + 1 : 0;
                const float4* src = (const float4*)(Wimg + (size_t)nxt * 65536 + 32768);
                float4* wl = (float4*)(sm + G3_WL);
#pragma unroll
                for (int q = 0; q < 8; q++) wl[tid + q * 256] = src[tid + q * 256];
            }
            FENCE_ASYNC_SHARED();
            __syncthreads();
            if (issuer && r < 2) {
                mma_pass3(tmem + (r + 1) * 128, aH, aL,
                          MAKE_SMEM_DESC(smb + G3_WH + (r + 1) * 32768), bLo);
                TCGEN05_COMMIT(smb + G3_MB + 8 * (r + 1));
            }
            int grow = row0 + rb;
            bool ok = grow < M;
            float rs = ok ? dinv_o[r * NN + grow] : 0.f;
            __half* op = mouts[r] + (size_t)grow * DIM;
#pragma unroll
            for (int hh = 0; hh < 2; hh++) {
                int cb = chalf + hh * 32;
                uint32_t dr[32];
                TCGEN05_LD_32X32B_X32(dr, tmem + r * 128 + cb);
                TCGEN05_WAIT_LD();
                if (ok) {
#pragma unroll
                    for (int j = 0; j < 8; j++) {
                        float4 c;
                        c.x = __uint_as_float(dr[4 * j + 0]) * rs;
                        c.y = __uint_as_float(dr[4 * j + 1]) * rs;
                        c.z = __uint_as_float(dr[4 * j + 2]) * rs;
                        c.w = __uint_as_float(dr[4 * j + 3]) * rs;
                        *(uint2*)(op + cb + 4 * j) = pack_half4(c);
                    }
                }
            }
        }
        __syncthreads();
        par ^= 1;
    }

    __syncthreads();
    if (wid == 0) TCGEN05_DEALLOC(tmem, 512);

#else  // fallback: persistent scalar
    float* Wf = (float*)sm;
    float* As = Wf + 16384;
    float* bns = As + 16 * 72;
    float* bnb = bns + DIM;

    if (BN && tid < DIM) {
        float mean = stats[tid] * (1.f / NN);
        float var = stats[DIM + tid] * (1.f / NN) - mean * mean;
        float inv = rsqrtf(var + BN_EPS);
        float sc = gamma[tid] * inv;
        bns[tid] = sc;
        bnb[tid] = beta[tid] - mean * sc;
    }
    __syncthreads();

    __half* mouts[3] = {m0, m1, m2};
    for (int tile = blockIdx.x; tile < MT; tile += gridDim.x) {
        int row0 = tile * 128;
        for (int r = 0; r < NR; r++) {
            for (int i = tid; i < 16384; i += 256) {
                int k = i >> 7, n = i & 127;
                uint32_t off = tile_off(n, k);
                const uint8_t* Wr = Wimg + (size_t)r * 65536;
                Wf[i] = __bfloat162float(*(const __nv_bfloat16*)(Wr + off)) +
                        __bfloat162float(*(const __nv_bfloat16*)(Wr + 32768 + off));
            }
            __syncthreads();

            int rbase = (tid >> 5) * 8;
            int cbase = (tid & 31) * 4;
            int arow = tid >> 2;
            int ak = (tid & 3) * 4;

            for (int halfb = 0; halfb < 2; halfb++) {
                int r0r = row0 + halfb * 64;
                int grow = r0r + arow;
                bool rowok = grow < M;
                const float4* Ar = A + (size_t)grow * 32;

                float acc[8][4];
#pragma unroll
                for (int i = 0; i < 8; i++)
#pragma unroll
                    for (int j = 0; j < 4; j++) acc[i][j] = 0.f;

                for (int kt = 0; kt < 8; ++kt) {
                    float4 av = rowok ? Ar[kt * 4 + (tid & 3)] : make_float4(0.f, 0.f, 0.f, 0.f);
                    if (BN) {
                        int c = kt * 16 + ak;
                        av.x = av.x * bns[c + 0] + bnb[c + 0];
                        av.y = av.y * bns[c + 1] + bnb[c + 1];
                        av.z = av.z * bns[c + 2] + bnb[c + 2];
                        av.w = av.w * bns[c + 3] + bnb[c + 3];
                    }
                    As[(ak + 0) * 72 + arow] = av.x;
                    As[(ak + 1) * 72 + arow] = av.y;
                    As[(ak + 2) * 72 + arow] = av.z;
                    As[(ak + 3) * 72 + arow] = av.w;
                    __syncthreads();
#pragma unroll
                    for (int kk = 0; kk < 16; ++kk) {
                        float4 b4 = *(float4*)&Wf[(kt * 16 + kk) * 128 + cbase];
                        float4 a0v = *(float4*)&As[kk * 72 + rbase];
                        float4 a1v = *(float4*)&As[kk * 72 + rbase + 4];
                        float a[8] = {a0v.x, a0v.y, a0v.z, a0v.w, a1v.x, a1v.y, a1v.z, a1v.w};
#pragma unroll
                        for (int i = 0; i < 8; i++) {
                            acc[i][0] += a[i] * b4.x;
                            acc[i][1] += a[i] * b4.y;
                            acc[i][2] += a[i] * b4.z;
                            acc[i][3] += a[i] * b4.w;
                        }
                    }
                    __syncthreads();
                }
#pragma unroll
                for (int i = 0; i < 8; i++) {
                    int rr = r0r + rbase + i;
                    if (rr < M) {
                        float rs = dinv_o[r * NN + rr];
                        float4 c;
                        c.x = acc[i][0] * rs; c.y = acc[i][1] * rs;
                        c.z = acc[i][2] * rs; c.w = acc[i][3] * rs;
                        *(uint2*)(mouts[r] + (size_t)rr * DIM + cbase) = pack_half4(c);
                    }
                }
            }
            __syncthreads();
        }
    }
#endif
}

// ---------------- FC GEMM (M=256 per CTA): C = relu(A @ W + bias) ----------------
#define SM_TMEM 0
#define SM_MBAR 8
#define SM_A 1024
#define SM_W (SM_A + 131072)
#define SM_TOTAL (SM_W + 65536)

__global__ void __launch_bounds__(256, 1) k_gemm_fc(const float4* __restrict__ A,
                                                    const uint8_t* __restrict__ Wimg,
                                                    const float* __restrict__ bias,
                                                    float* __restrict__ C, int M) {
    extern __shared__ char sm[];
    int tid = threadIdx.x, wid = tid >> 5, lid = tid & 31;
    int row0 = blockIdx.x * 256;

#if HAS_TCGEN05
    uint32_t smb = smem_u32(sm);
    if (tid == 0) MBARRIER_INIT(smb + SM_MBAR, 1);
    if (wid == 0) { TCGEN05_ALLOC(smb + SM_TMEM, 256); }
    __syncthreads();

    {
        const float4* Wv = (const float4*)Wimg;
        float4* Bv = (float4*)(sm + SM_W);
#pragma unroll
        for (int i = 0; i < 16; i++) Bv[tid + i * 256] = Wv[tid + i * 256];
    }

#pragma unroll
    for (int g = 0; g < 4; g++) {
        float4 buf[8];
        int idx[8];
#pragma unroll
        for (int b = 0; b < 8; b++) {
            int i = g * 2048 + b * 256 + tid;
            idx[b] = i;
            int grow = row0 + (i >> 5);
            buf[b] = (grow < M) ? A[(size_t)grow * 32 + (i & 31)] : make_float4(0.f, 0.f, 0.f, 0.f);
        }
#pragma unroll
        for (int b = 0; b < 8; b++) {
            int i = idx[b];
            int row = i >> 5, c4 = i & 31;
            int t = row >> 7, lrow = row & 127;
            split_store(sm + SM_A + t * 65536, sm + SM_A + t * 65536 + 32768,
                        tile_off(lrow, c4 * 4), buf[b]);
        }
    }

    FENCE_ASYNC_SHARED();
    __syncthreads();

    uint32_t tmem;
    asm volatile("ld.shared.b32 %0, [%1];" : "=r"(tmem) : "r"(smb + SM_TMEM));

    if (wid == 0 && elect_one()) {
        uint64_t bH = MAKE_SMEM_DESC(smb + SM_W);
        uint64_t bL = MAKE_SMEM_DESC(smb + SM_W + 32768);
#pragma unroll
        for (int t = 0; t < 2; t++) {
            uint64_t aH = MAKE_SMEM_DESC(smb + SM_A + t * 65536);
            uint64_t aL = MAKE_SMEM_DESC(smb + SM_A + t * 65536 + 32768);
            mma_pass3(tmem + t * 128, aH, aL, bH, bL);
        }
        TCGEN05_COMMIT(smb + SM_MBAR);
    }

    mbar_wait(smb + SM_MBAR, 0);
    TCGEN05_FENCE_AFTER();

#pragma unroll
    for (int t = 0; t < 2; t++) {
        int rb = t * 128 + (wid & 3) * 32 + lid;
        int grow = row0 + rb;
        int chalf = (wid >> 2) * 64;
#pragma unroll
        for (int hh = 0; hh < 2; hh++) {
            int cb = chalf + hh * 32;
            uint32_t dr[32];
            TCGEN05_LD_32X32B_X32(dr, tmem + t * 128 + cb);
            TCGEN05_WAIT_LD();
            if (grow < M) {
                float* op = C + (size_t)grow * DIM + cb;
#pragma unroll
                for (int j = 0; j < 8; j++) {
                    float4 bv = *(const float4*)(bias + cb + 4 * j);
                    float4 c;
                    c.x = fmaxf(__uint_as_float(dr[4 * j + 0]) + bv.x, 0.f);
                    c.y = fmaxf(__uint_as_float(dr[4 * j + 1]) + bv.y, 0.f);
                    c.z = fmaxf(__uint_as_float(dr[4 * j + 2]) + bv.z, 0.f);
                    c.w = fmaxf(__uint_as_float(dr[4 * j + 3]) + bv.w, 0.f);
                    *(float4*)(op + 4 * j) = c;
                }
            }
        }
    }

    __syncthreads();
    if (wid == 0) TCGEN05_DEALLOC(tmem, 256);

#else  // fallback
    float* Wf = (float*)sm;
    float* As = Wf + 16384;

    for (int i = tid; i < 16384; i += 256) {
        int k = i >> 7, n = i & 127;
        uint32_t off = tile_off(n, k);
        Wf[i] = __bfloat162float(*(const __nv_bfloat16*)(Wimg + off)) +
                __bfloat162float(*(const __nv_bfloat16*)(Wimg + 32768 + off));
    }
    __syncthreads();

    int rbase = (tid >> 5) * 8;
    int cbase = (tid & 31) * 4;
    int arow = tid >> 2;
    int ak = (tid & 3) * 4;

    for (int half = 0; half < 4; half++) {
        int r0 = row0 + half * 64;
        int grow = r0 + arow;
        bool rowok = grow < M;
        const float4* Ar = A + (size_t)grow * 32;

        float acc[8][4];
#pragma unroll
        for (int i = 0; i < 8; i++)
#pragma unroll
            for (int j = 0; j < 4; j++) acc[i][j] = 0.f;

        for (int kt = 0; kt < 8; ++kt) {
            float4 av = rowok ? Ar[kt * 4 + (tid & 3)] : make_float4(0.f, 0.f, 0.f, 0.f);
            As[(ak + 0) * 72 + arow] = av.x;
            As[(ak + 1) * 72 + arow] = av.y;
            As[(ak + 2) * 72 + arow] = av.z;
            As[(ak + 3) * 72 + arow] = av.w;
            __syncthreads();
#pragma unroll
            for (int kk = 0; kk < 16; ++kk) {
                float4 b4 = *(float4*)&Wf[(kt * 16 + kk) * 128 + cbase];
                float4 a0v = *(float4*)&As[kk * 72 + rbase];
                float4 a1v = *(float4*)&As[kk * 72 + rbase + 4];
                float a[8] = {a0v.x, a0v.y, a0v.z, a0v.w, a1v.x, a1v.y, a1v.z, a1v.w};
#pragma unroll
                for (int i = 0; i < 8; i++) {
                    acc[i][0] += a[i] * b4.x;
                    acc[i][1] += a[i] * b4.y;
                    acc[i][2] += a[i] * b4.z;
                    acc[i][3] += a[i] * b4.w;
                }
            }
            __syncthreads();
        }

        float4 bv = *(const float4*)(bias + cbase);
#pragma unroll
        for (int i = 0; i < 8; i++) {
            int r = r0 + rbase + i;
            if (r < M) {
                float4 c;
                c.x = fmaxf(acc[i][0] + bv.x, 0.f);
                c.y = fmaxf(acc[i][1] + bv.y, 0.f);
                c.z = fmaxf(acc[i][2] + bv.z, 0.f);
                c.w = fmaxf(acc[i][3] + bv.w, 0.f);
                *(float4*)(C + (size_t)r * DIM + cbase) = c;
            }
        }
    }
#endif
}

// ---------------- BatchNorm ----------------
__global__ void __launch_bounds__(128) k_bnstats(const float* __restrict__ h, float* __restrict__ stats) {
    int c = threadIdx.x;
    float s = 0.f, s2 = 0.f;
    for (int r = blockIdx.x; r < NN; r += gridDim.x) {
        float v = h[(size_t)r * DIM + c];
        s += v;
        s2 += v * v;
    }
    atomicAdd(&stats[c], s);
    atomicAdd(&stats[DIM + c], s2);
}
__global__ void __launch_bounds__(256) k_bnnorm(const float* __restrict__ h,
                                                const float* __restrict__ stats,
                                                const float* __restrict__ gamma,
                                                const float* __restrict__ beta,
                                                float* __restrict__ out) {
    int i = blockIdx.x * 256 + threadIdx.x;
    if (i >= NN * DIM / 4) return;
    int c = (i & 31) * 4;
    float4 v = *(const float4*)(h + (size_t)i * 4);
    float vin[4] = {v.x, v.y, v.z, v.w};
    float o[4];
#pragma unroll
    for (int j = 0; j < 4; j++) {
        float mean = stats[c + j] * (1.f / NN);
        float var = stats[DIM + c + j] * (1.f / NN) - mean * mean;
        float inv = rsqrtf(var + BN_EPS);
        o[j] = (vin[j] - mean) * inv * gamma[c + j] + beta[c + j];
    }
    *(float4*)(out + (size_t)i * 4) = make_float4(o[0], o[1], o[2], o[3]);
}

// ---------------- launch ----------------
extern "C" void kernel_launch(void* const* d_in, const int* in_sizes, int n_in,
                              void* d_out, int out_size) {
    const float* x      = (const float*)d_in[0];
    const int*   edges  = (const int*)d_in[1];
    const float* conv_W = (const float*)d_in[2];
    const float* conv_b = (const float*)d_in[3];
    const float* fc_W   = (const float*)d_in[4];
    const float* fc_b   = (const float*)d_in[5];
    const float* gamma  = (const float*)d_in[6];
    const float* beta   = (const float*)d_in[7];
    float* out = (float*)d_out;

    float *h, *agg, *dinv_o, *dinv_i, *stats3, *fceff;
    __half *m0, *m1, *m2;
    int *cnt_in, *cnt_out, *cursor, *excl, *bsum, *srcidx;
    uint8_t* wbf;
    cudaGetSymbolAddress((void**)&h, g_h);
    cudaGetSymbolAddress((void**)&m0, g_m0);
    cudaGetSymbolAddress((void**)&m1, g_m1);
    cudaGetSymbolAddress((void**)&m2, g_m2);
    cudaGetSymbolAddress((void**)&agg, g_agg);
    cudaGetSymbolAddress((void**)&dinv_o, g_dinv_o);
    cudaGetSymbolAddress((void**)&dinv_i, g_dinv_i);
    cudaGetSymbolAddress((void**)&cnt_in, g_cnt_in);
    cudaGetSymbolAddress((void**)&cnt_out, g_cnt_out);
    cudaGetSymbolAddress((void**)&cursor, g_cursor);
    cudaGetSymbolAddress((void**)&excl, g_excl);
    cudaGetSymbolAddress((void**)&bsum, g_bsum);
    cudaGetSymbolAddress((void**)&srcidx, g_srcidx);
    cudaGetSymbolAddress((void**)&stats3, g_stats3);
    cudaGetSymbolAddress((void**)&wbf, g_Wbf);
    cudaGetSymbolAddress((void**)&fceff, g_fceff);

    cudaFuncSetAttribute(k_gemm3<false>, cudaFuncAttributeMaxDynamicSharedMemorySize, G3_TOTAL);
    cudaFuncSetAttribute(k_gemm3<true>, cudaFuncAttributeMaxDynamicSharedMemorySize, G3_TOTAL);
    cudaFuncSetAttribute(k_gemm_fc, cudaFuncAttributeMaxDynamicSharedMemorySize, SM_TOTAL);

    const int nh4 = NN * DIM / 4;
    const int NSC = NR * NN;
    const int NB1 = (NSC + 1023) / 1024;

    // ---- prep ----
    k_wprep<<<(12 * 16384 + 255) / 256, 256>>>(conv_W, fc_W, wbf);
    k_bprep<<<NL, 128>>>(conv_b, fc_W, fc_b, fceff);
    k_zeroprep<<<(NSC + 255) / 256, 256>>>(cnt_in, cnt_out, cursor, stats3, NSC);
    k_cnt<<<(NR * NE + 255) / 256, 256>>>(edges, cnt_out, cnt_in);
    k_dinv<<<(NSC + 255) / 256, 256>>>(cnt_out, cnt_in, dinv_o, dinv_i);
    k_scan1<<<NB1, 1024>>>(cnt_in, excl, bsum, NSC);
    k_scan2<<<1, 512>>>(bsum, NB1);
    k_scan3<<<NB1, 1024>>>(excl, bsum, NSC);
    k_place<<<(NR * NE + 255) / 256, 256>>>(edges, excl, cursor, srcidx);

    const int GGRID = (NN * 32 + 255) / 256;
    const int FCGRID = (NN + 255) / 256;     // 391

    for (int l = 0; l < NL; ++l) {
        if (l == 0)
            k_gemm3<false><<<148, 256, G3_TOTAL>>>(
                (const float4*)x, wbf + (size_t)(l * NR) * 65536,
                nullptr, nullptr, nullptr, dinv_o, m0, m1, m2, NN);
        else
            k_gemm3<true><<<148, 256, G3_TOTAL>>>(
                (const float4*)h, wbf + (size_t)(l * NR) * 65536,
                stats3 + (size_t)(l - 1) * 2 * DIM,
                gamma + (size_t)(l - 1) * DIM, beta + (size_t)(l - 1) * DIM,
                dinv_o, m0, m1, m2, NN);
        k_gather3<<<GGRID, 256>>>(m0, m1, m2, srcidx, excl, cnt_in, dinv_i, agg);
        k_gemm_fc<<<FCGRID, 256, SM_TOTAL>>>((const float4*)agg,
                                             wbf + (size_t)(9 + l) * 65536,
                                             fceff + (size_t)l * DIM, h, NN);
        k_bnstats<<<1024, 128>>>(h, stats3 + (size_t)l * 2 * DIM);
    }
    k_bnnorm<<<(nh4 + 255) / 256, 256>>>(h, stats3 + (size_t)(NL - 1) * 2 * DIM,
                                         gamma + (size_t)(NL - 1) * DIM,
                                         beta + (size_t)(NL - 1) * DIM, out);
}